// round 2
// baseline (speedup 1.0000x reference)
#include <cuda_runtime.h>

#define Bn 8
#define Nn 1024
#define En 256
#define Hn 8
#define Dn 32
#define Cn 4

// ---- packed f32x2 helpers (sm_103a FFMA2) ----
typedef unsigned long long f32x2;

__device__ __forceinline__ f32x2 pack2(float lo, float hi) {
    f32x2 r;
    asm("mov.b64 %0, {%1, %2};" : "=l"(r) : "f"(lo), "f"(hi));
    return r;
}
__device__ __forceinline__ void unpack2(f32x2 v, float& lo, float& hi) {
    asm("mov.b64 {%0, %1}, %2;" : "=f"(lo), "=f"(hi) : "l"(v));
}
__device__ __forceinline__ f32x2 fma2(f32x2 a, f32x2 b, f32x2 c) {
    f32x2 d;
    asm("fma.rn.f32x2 %0, %1, %2, %3;" : "=l"(d) : "l"(a), "l"(b), "l"(c));
    return d;
}
__device__ __forceinline__ f32x2 mul2(f32x2 a, f32x2 b) {
    f32x2 d;
    asm("mul.rn.f32x2 %0, %1, %2;" : "=l"(d) : "l"(a), "l"(b));
    return d;
}

// ---- scratch ----
__device__ float d_Q[Bn * Hn * Nn * Dn];
__device__ float d_K[Bn * Hn * Nn * Dn];
__device__ float d_V[Bn * Hn * Nn * Dn];
__device__ float d_ctx[Bn * Hn * Nn * Dn];

// ============================================================================
// GEMM tiles: 128x128x8, 256 threads, 8x8 per thread, packed f32x2 math.
// ============================================================================
#define BM 128
#define BN 128
#define BK 8
#define BMP (BM + 4)   // padded row to kill As scatter-store conflicts

__global__ __launch_bounds__(256)
void gemm_qkv(const float* __restrict__ X,
              const float* __restrict__ Wq, const float* __restrict__ bq,
              const float* __restrict__ Wk, const float* __restrict__ bk,
              const float* __restrict__ Wv, const float* __restrict__ bv)
{
    __shared__ __align__(16) float As[BK][BMP];
    __shared__ __align__(16) float Bs[BK][BN];

    const int z = blockIdx.z;
    const float* __restrict__ W    = (z == 0) ? Wq : (z == 1) ? Wk : Wv;
    const float* __restrict__ bias = (z == 0) ? bq : (z == 1) ? bk : bv;
    float* __restrict__ Out        = (z == 0) ? d_Q : (z == 1) ? d_K : d_V;

    const int tid  = threadIdx.x;
    const int row0 = blockIdx.y * BM;
    const int col0 = blockIdx.x * BN;
    const int tx = tid & 15;          // n group
    const int ty = tid >> 4;          // m group
    const int m0 = ty * 8;
    const int n0 = tx * 8;

    const int a_m = tid >> 1;         // 0..127
    const int a_k = (tid & 1) * 4;    // 0 or 4
    const int b_k = tid >> 5;         // 0..7
    const int b_n = (tid & 31) * 4;   // 0..124

    f32x2 acc[8][4];
#pragma unroll
    for (int m = 0; m < 8; m++)
#pragma unroll
        for (int n = 0; n < 4; n++) acc[m][n] = 0ULL;

    for (int k0 = 0; k0 < En; k0 += BK) {
        float4 av = *(const float4*)&X[(row0 + a_m) * En + k0 + a_k];
        As[a_k + 0][a_m] = av.x;
        As[a_k + 1][a_m] = av.y;
        As[a_k + 2][a_m] = av.z;
        As[a_k + 3][a_m] = av.w;
        *(float4*)&Bs[b_k][b_n] = *(const float4*)&W[(k0 + b_k) * En + col0 + b_n];
        __syncthreads();
#pragma unroll
        for (int k = 0; k < BK; k++) {
            float4 a0 = *(const float4*)&As[k][m0];
            float4 a1 = *(const float4*)&As[k][m0 + 4];
            ulonglong2 bb0 = *(const ulonglong2*)&Bs[k][n0];
            ulonglong2 bb1 = *(const ulonglong2*)&Bs[k][n0 + 4];
            f32x2 b2[4] = {bb0.x, bb0.y, bb1.x, bb1.y};
            float am[8] = {a0.x, a0.y, a0.z, a0.w, a1.x, a1.y, a1.z, a1.w};
#pragma unroll
            for (int m = 0; m < 8; m++) {
                f32x2 a2 = pack2(am[m], am[m]);
#pragma unroll
                for (int n = 0; n < 4; n++)
                    acc[m][n] = fma2(a2, b2[n], acc[m][n]);
            }
        }
        __syncthreads();
    }

    // epilogue: write into [B,H,N,D] head layout
#pragma unroll
    for (int half = 0; half < 2; half++) {
        int c = col0 + n0 + half * 4;       // 4 consecutive cols, within one head
        int h = c >> 5, dd = c & 31;
        float4 bz = *(const float4*)&bias[c];
#pragma unroll
        for (int m = 0; m < 8; m++) {
            int gm = row0 + m0 + m;
            int b = gm >> 10, n = gm & 1023;
            float x0, x1, x2, x3;
            unpack2(acc[m][half * 2 + 0], x0, x1);
            unpack2(acc[m][half * 2 + 1], x2, x3);
            float4 o;
            o.x = x0 + bz.x; o.y = x1 + bz.y; o.z = x2 + bz.z; o.w = x3 + bz.w;
            *(float4*)&Out[((b * Hn + h) * Nn + n) * Dn + dd] = o;
        }
    }
}

// ============================================================================
// Fused adjacency-bias flash attention (packed f32x2 math).
// ============================================================================
#define TM 32
#define TJ 16

__global__ __launch_bounds__(256)
void attn_kernel(const float* __restrict__ adj,
                 const float* __restrict__ Wa,
                 const float* __restrict__ ba)
{
    __shared__ __align__(16) float Ks[Hn][TJ][Dn];
    __shared__ __align__(16) float Vs[Hn][TJ][Dn];
    __shared__ __align__(16) float Adjs[TJ][Cn][TM];

    const int tid  = threadIdx.x;
    const int h    = tid >> 5;
    const int i    = tid & 31;
    const int bIdx = blockIdx.x >> 5;
    const int tile = blockIdx.x & 31;
    const int row  = tile * TM + i;

    f32x2 q2[Dn / 2];
    {
        const ulonglong2* qp = (const ulonglong2*)&d_Q[((bIdx * Hn + h) * Nn + row) * Dn];
#pragma unroll
        for (int t = 0; t < Dn / 4; t++) {
            ulonglong2 v = qp[t];
            q2[2 * t] = v.x; q2[2 * t + 1] = v.y;
        }
    }
    float wa[Cn];
#pragma unroll
    for (int c = 0; c < Cn; c++) wa[c] = Wa[c * Hn + h];
    const float bah = ba[h];

    float mrun = -1e30f, l = 0.f;
    f32x2 acc2[Dn / 2];
#pragma unroll
    for (int d = 0; d < Dn / 2; d++) acc2[d] = 0ULL;
    const float scale = 0.17677669529663687f;  // 1/sqrt(32)

    for (int j0 = 0; j0 < Nn; j0 += TJ) {
        // stage K,V: 8*16*32 floats each; 4 float4 per thread per array
#pragma unroll
        for (int u = 0; u < 4; u++) {
            int idx = tid + u * 256;
            int hh = idx >> 7;
            int rr = idx & 127;
            int jj = rr >> 3;
            int dd = (rr & 7) * 4;
            int goff = ((bIdx * Hn + hh) * Nn + j0 + jj) * Dn + dd;
            *(float4*)&Ks[hh][jj][dd] = *(const float4*)&d_K[goff];
            *(float4*)&Vs[hh][jj][dd] = *(const float4*)&d_V[goff];
        }
        // stage adj tile, transposed to [j][c][i]
#pragma unroll
        for (int u = 0; u < 2; u++) {
            int idx = tid + u * 256;
            int ii = idx >> 4;
            int jj = idx & 15;
            float4 a4 = *(const float4*)&adj[((bIdx * Nn + tile * TM + ii) * Nn + (j0 + jj)) * Cn];
            Adjs[jj][0][ii] = a4.x;
            Adjs[jj][1][ii] = a4.y;
            Adjs[jj][2][ii] = a4.z;
            Adjs[jj][3][ii] = a4.w;
        }
        __syncthreads();

        float s[TJ];
        float tmax = -1e30f;
#pragma unroll
        for (int j = 0; j < TJ; j++) {
            const ulonglong2* kp = (const ulonglong2*)&Ks[h][j][0];
            f32x2 sv2 = 0ULL;
#pragma unroll
            for (int t = 0; t < Dn / 4; t++) {
                ulonglong2 kk = kp[t];
                sv2 = fma2(q2[2 * t], kk.x, sv2);
                sv2 = fma2(q2[2 * t + 1], kk.y, sv2);
            }
            float slo, shi;
            unpack2(sv2, slo, shi);
            float bv = bah;
#pragma unroll
            for (int c = 0; c < Cn; c++) bv += Adjs[j][c][i] * wa[c];
            float sv = (slo + shi) * scale + bv;
            s[j] = sv;
            tmax = fmaxf(tmax, sv);
        }

        float mnew = fmaxf(mrun, tmax);
        float corr = __expf(mrun - mnew);
        l *= corr;
        f32x2 corr2 = pack2(corr, corr);
#pragma unroll
        for (int d = 0; d < Dn / 2; d++) acc2[d] = mul2(acc2[d], corr2);

#pragma unroll
        for (int j = 0; j < TJ; j++) {
            float p = __expf(s[j] - mnew);
            l += p;
            f32x2 p2 = pack2(p, p);
            const ulonglong2* vp = (const ulonglong2*)&Vs[h][j][0];
#pragma unroll
            for (int t = 0; t < Dn / 4; t++) {
                ulonglong2 vv = vp[t];
                acc2[2 * t]     = fma2(p2, vv.x, acc2[2 * t]);
                acc2[2 * t + 1] = fma2(p2, vv.y, acc2[2 * t + 1]);
            }
        }
        mrun = mnew;
        __syncthreads();
    }

    const float inv = 1.f / l;
    float out[Dn];
#pragma unroll
    for (int d = 0; d < Dn / 2; d++) {
        float lo, hi;
        unpack2(acc2[d], lo, hi);
        out[2 * d] = lo * inv;
        out[2 * d + 1] = hi * inv;
    }
    float4* op = (float4*)&d_ctx[((bIdx * Hn + h) * Nn + row) * Dn];
#pragma unroll
    for (int t = 0; t < Dn / 4; t++) {
        float4 o;
        o.x = out[4 * t]; o.y = out[4 * t + 1]; o.z = out[4 * t + 2]; o.w = out[4 * t + 3];
        op[t] = o;
    }
}

// ============================================================================
// Output projection + residual (same tiling as gemm_qkv, A gathered from ctx).
// ============================================================================
__global__ __launch_bounds__(256)
void gemm_out(const float* __restrict__ X,
              const float* __restrict__ Wo, const float* __restrict__ bo,
              float* __restrict__ Out)
{
    __shared__ __align__(16) float As[BK][BMP];
    __shared__ __align__(16) float Bs[BK][BN];

    const int tid  = threadIdx.x;
    const int row0 = blockIdx.y * BM;
    const int col0 = blockIdx.x * BN;
    const int tx = tid & 15;
    const int ty = tid >> 4;
    const int m0 = ty * 8;
    const int n0 = tx * 8;

    const int a_m = tid >> 1;
    const int a_k = (tid & 1) * 4;
    const int b_k = tid >> 5;
    const int b_n = (tid & 31) * 4;

    const int am_g = row0 + a_m;
    const int am_b = am_g >> 10, am_n = am_g & 1023;

    f32x2 acc[8][4];
#pragma unroll
    for (int m = 0; m < 8; m++)
#pragma unroll
        for (int n = 0; n < 4; n++) acc[m][n] = 0ULL;

    for (int k0 = 0; k0 < En; k0 += BK) {
        int k  = k0 + a_k;
        int hh = k >> 5, dd = k & 31;
        float4 av = *(const float4*)&d_ctx[((am_b * Hn + hh) * Nn + am_n) * Dn + dd];
        As[a_k + 0][a_m] = av.x;
        As[a_k + 1][a_m] = av.y;
        As[a_k + 2][a_m] = av.z;
        As[a_k + 3][a_m] = av.w;
        *(float4*)&Bs[b_k][b_n] = *(const float4*)&Wo[(k0 + b_k) * En + col0 + b_n];
        __syncthreads();
#pragma unroll
        for (int k2 = 0; k2 < BK; k2++) {
            float4 a0 = *(const float4*)&As[k2][m0];
            float4 a1 = *(const float4*)&As[k2][m0 + 4];
            ulonglong2 bb0 = *(const ulonglong2*)&Bs[k2][n0];
            ulonglong2 bb1 = *(const ulonglong2*)&Bs[k2][n0 + 4];
            f32x2 b2[4] = {bb0.x, bb0.y, bb1.x, bb1.y};
            float am[8] = {a0.x, a0.y, a0.z, a0.w, a1.x, a1.y, a1.z, a1.w};
#pragma unroll
            for (int m = 0; m < 8; m++) {
                f32x2 a2 = pack2(am[m], am[m]);
#pragma unroll
                for (int n = 0; n < 4; n++)
                    acc[m][n] = fma2(a2, b2[n], acc[m][n]);
            }
        }
        __syncthreads();
    }

#pragma unroll
    for (int half = 0; half < 2; half++) {
        int c = col0 + n0 + half * 4;
        float4 bz = *(const float4*)&bo[c];
#pragma unroll
        for (int m = 0; m < 8; m++) {
            int gm = row0 + m0 + m;
            float4 xr = *(const float4*)&X[gm * En + c];
            float x0, x1, x2, x3;
            unpack2(acc[m][half * 2 + 0], x0, x1);
            unpack2(acc[m][half * 2 + 1], x2, x3);
            float4 o;
            o.x = x0 + bz.x + xr.x;
            o.y = x1 + bz.y + xr.y;
            o.z = x2 + bz.z + xr.z;
            o.w = x3 + bz.w + xr.w;
            *(float4*)&Out[gm * En + c] = o;
        }
    }
}

// ============================================================================
extern "C" void kernel_launch(void* const* d_in, const int* in_sizes, int n_in,
                              void* d_out, int out_size)
{
    const float* x   = (const float*)d_in[0];
    const float* adj = (const float*)d_in[1];
    const float* Wq  = (const float*)d_in[2];
    const float* bq  = (const float*)d_in[3];
    const float* Wk  = (const float*)d_in[4];
    const float* bk  = (const float*)d_in[5];
    const float* Wv  = (const float*)d_in[6];
    const float* bv  = (const float*)d_in[7];
    const float* Wo  = (const float*)d_in[8];
    const float* bo  = (const float*)d_in[9];
    const float* Wa  = (const float*)d_in[10];
    const float* ba  = (const float*)d_in[11];
    float* out = (float*)d_out;

    dim3 gq(En / BN, (Bn * Nn) / BM, 3);       // (2, 64, 3)
    gemm_qkv<<<gq, 256>>>(x, Wq, bq, Wk, bk, Wv, bv);

    attn_kernel<<<Bn * (Nn / TM), 256>>>(adj, Wa, ba);

    dim3 go(En / BN, (Bn * Nn) / BM);          // (2, 64)
    gemm_out<<<go, 256>>>(x, Wo, bo, out);
}

// round 4
// speedup vs baseline: 2.1148x; 2.1148x over previous
#include <cuda_runtime.h>
#include <cuda_bf16.h>
#include <cuda_fp16.h>
#include <cstdint>

#define Bn 8
#define Nn 1024
#define En 256
#define Hn 8
#define Dn 32
#define Cn 4

// ---- scratch ----
#define QSZ (Bn * Hn * Nn * Dn)            // 2M
__device__ float d_Q[QSZ];
__device__ float d_K[QSZ];
__device__ float d_V[QSZ];
__device__ float d_ctx[QSZ];
__device__ __nv_bfloat16 g_qhi[QSZ], g_qlo[QSZ];
__device__ __nv_bfloat16 g_khi[QSZ], g_klo[QSZ];
__device__ __nv_bfloat16 g_vthi[QSZ], g_vtlo[QSZ];   // [B,H,D,N]
__device__ __half g_bias[(size_t)Bn * Hn * Nn * Nn]; // 134MB, log2e-scaled

// 1/sqrt(32) * log2(e)
#define SCALEQ 0.25506807163967554f
#define LOG2E  1.4426950408889634f

__device__ __forceinline__ float ex2(float x) {
    float y;
    asm("ex2.approx.f32 %0, %1;" : "=f"(y) : "f"(x));
    return y;
}
__device__ __forceinline__ uint32_t bits2(__nv_bfloat162 v) {
    return *reinterpret_cast<uint32_t*>(&v);
}
__device__ __forceinline__ uint2 pack4bf(float a, float b, float c, float d) {
    __nv_bfloat162 lo = __floats2bfloat162_rn(a, b);
    __nv_bfloat162 hi = __floats2bfloat162_rn(c, d);
    uint2 r;
    r.x = bits2(lo);
    r.y = bits2(hi);
    return r;
}

#define MMA(c, a, b0, b1)                                                     \
    asm volatile("mma.sync.aligned.m16n8k16.row.col.f32.bf16.bf16.f32 "       \
        "{%0,%1,%2,%3}, {%4,%5,%6,%7}, {%8,%9}, {%0,%1,%2,%3};"               \
        : "+f"((c)[0]), "+f"((c)[1]), "+f"((c)[2]), "+f"((c)[3])              \
        : "r"((a)[0]), "r"((a)[1]), "r"((a)[2]), "r"((a)[3]), "r"(b0), "r"(b1))

// ============================================================================
// Kernel 1: scalar QKV projection GEMM (R1, known-good). 64x64x16 tiles.
// ============================================================================
#define BM 64
#define BN 64
#define BK 16

__global__ __launch_bounds__(256)
void gemm_qkv(const float* __restrict__ X,
              const float* __restrict__ Wq, const float* __restrict__ bq,
              const float* __restrict__ Wk, const float* __restrict__ bk,
              const float* __restrict__ Wv, const float* __restrict__ bv)
{
    __shared__ float As[BK][BM + 4];
    __shared__ float Bs[BK][BN];

    const int z = blockIdx.z;
    const float* __restrict__ W    = (z == 0) ? Wq : (z == 1) ? Wk : Wv;
    const float* __restrict__ bias = (z == 0) ? bq : (z == 1) ? bk : bv;
    float* __restrict__ Out        = (z == 0) ? d_Q : (z == 1) ? d_K : d_V;

    const int tid  = threadIdx.x;
    const int row0 = blockIdx.y * BM;
    const int col0 = blockIdx.x * BN;
    const int tx = tid & 15;
    const int ty = tid >> 4;

    const int a_m = tid >> 2;
    const int a_k = (tid & 3) * 4;
    const int b_k = tid >> 4;
    const int b_n = (tid & 15) * 4;

    float acc[4][4] = {};

    for (int k0 = 0; k0 < En; k0 += BK) {
        float4 av = *(const float4*)&X[(row0 + a_m) * En + k0 + a_k];
        As[a_k + 0][a_m] = av.x;
        As[a_k + 1][a_m] = av.y;
        As[a_k + 2][a_m] = av.z;
        As[a_k + 3][a_m] = av.w;
        *(float4*)&Bs[b_k][b_n] = *(const float4*)&W[(k0 + b_k) * En + col0 + b_n];
        __syncthreads();
#pragma unroll
        for (int k = 0; k < BK; k++) {
            float4 a4 = *(const float4*)&As[k][ty * 4];
            float4 b4 = *(const float4*)&Bs[k][tx * 4];
            acc[0][0] += a4.x * b4.x; acc[0][1] += a4.x * b4.y; acc[0][2] += a4.x * b4.z; acc[0][3] += a4.x * b4.w;
            acc[1][0] += a4.y * b4.x; acc[1][1] += a4.y * b4.y; acc[1][2] += a4.y * b4.z; acc[1][3] += a4.y * b4.w;
            acc[2][0] += a4.z * b4.x; acc[2][1] += a4.z * b4.y; acc[2][2] += a4.z * b4.z; acc[2][3] += a4.z * b4.w;
            acc[3][0] += a4.w * b4.x; acc[3][1] += a4.w * b4.y; acc[3][2] += a4.w * b4.z; acc[3][3] += a4.w * b4.w;
        }
        __syncthreads();
    }

    const int c  = col0 + tx * 4;
    const int h  = c >> 5;
    const int dd = c & 31;
    float4 bz = *(const float4*)&bias[c];
#pragma unroll
    for (int i = 0; i < 4; i++) {
        int m = row0 + ty * 4 + i;
        int b = m >> 10, n = m & 1023;
        float4 o;
        o.x = acc[i][0] + bz.x;
        o.y = acc[i][1] + bz.y;
        o.z = acc[i][2] + bz.z;
        o.w = acc[i][3] + bz.w;
        *(float4*)&Out[((b * Hn + h) * Nn + n) * Dn + dd] = o;
    }
}

// ============================================================================
// Kernel 2: convert Q (scale+split) and K (split) to bf16 hi/lo
// ============================================================================
__global__ __launch_bounds__(256)
void convert_qk()
{
    int i = blockIdx.x * 256 + threadIdx.x;        // per float4, 512K total
    float4 q = ((const float4*)d_Q)[i];
    q.x *= SCALEQ; q.y *= SCALEQ; q.z *= SCALEQ; q.w *= SCALEQ;
    float v[4] = {q.x, q.y, q.z, q.w};
    float hi[4], lo[4];
#pragma unroll
    for (int t = 0; t < 4; t++) {
        hi[t] = __bfloat162float(__float2bfloat16_rn(v[t]));
        lo[t] = v[t] - hi[t];
    }
    ((uint2*)g_qhi)[i] = pack4bf(hi[0], hi[1], hi[2], hi[3]);
    ((uint2*)g_qlo)[i] = pack4bf(lo[0], lo[1], lo[2], lo[3]);

    float4 k = ((const float4*)d_K)[i];
    float kv[4] = {k.x, k.y, k.z, k.w};
#pragma unroll
    for (int t = 0; t < 4; t++) {
        hi[t] = __bfloat162float(__float2bfloat16_rn(kv[t]));
        lo[t] = kv[t] - hi[t];
    }
    ((uint2*)g_khi)[i] = pack4bf(hi[0], hi[1], hi[2], hi[3]);
    ((uint2*)g_klo)[i] = pack4bf(lo[0], lo[1], lo[2], lo[3]);
}

// ============================================================================
// Kernel 3: transpose V to [B,H,D,N] + split
// ============================================================================
__global__ __launch_bounds__(256)
void transpose_v()
{
    __shared__ float T[32][36];
    const int tid = threadIdx.x;
    const int blk = blockIdx.x;            // bh*32 + jt
    const int bh = blk >> 5, jt = blk & 31;
    const int j0 = jt * 32;
    {
        int r = tid >> 3, c = tid & 7;
        float4 v = *(const float4*)&d_V[(bh * Nn + j0 + r) * Dn + c * 4];
        *(float4*)&T[r][c * 4] = v;
    }
    __syncthreads();
    {
        int d = tid >> 3, c = tid & 7;
        float f[4], hi[4], lo[4];
#pragma unroll
        for (int u = 0; u < 4; u++) {
            f[u] = T[c * 4 + u][d];
            hi[u] = __bfloat162float(__float2bfloat16_rn(f[u]));
            lo[u] = f[u] - hi[u];
        }
        int off = (bh * Dn + d) * Nn + j0 + c * 4;
        *(uint2*)&g_vthi[off] = pack4bf(hi[0], hi[1], hi[2], hi[3]);
        *(uint2*)&g_vtlo[off] = pack4bf(lo[0], lo[1], lo[2], lo[3]);
    }
}

// ============================================================================
// Kernel 4: bias precompute  bias[b,h,i,j] = (adj[b,i,j,:]@Wa[:,h] + ba[h])*log2e
// ============================================================================
__global__ __launch_bounds__(256)
void bias_pre(const float* __restrict__ adj, const float* __restrict__ Wa,
              const float* __restrict__ ba)
{
    const int tid = threadIdx.x;
    const int b = blockIdx.x >> 10;
    const int i = blockIdx.x & 1023;
    float w2[Cn][Hn], off[Hn];
#pragma unroll
    for (int h = 0; h < Hn; h++) {
        off[h] = ba[h] * LOG2E;
#pragma unroll
        for (int c = 0; c < Cn; c++) w2[c][h] = Wa[c * Hn + h] * LOG2E;
    }
    const float4* a4 = (const float4*)&adj[(size_t)(b * Nn + i) * Nn * Cn];
#pragma unroll
    for (int r = 0; r < 2; r++) {
        int j = (tid + r * 256) * 2;
        float4 x0 = a4[j];
        float4 x1 = a4[j + 1];
#pragma unroll
        for (int h = 0; h < Hn; h++) {
            float v0 = off[h] + x0.x * w2[0][h] + x0.y * w2[1][h] + x0.z * w2[2][h] + x0.w * w2[3][h];
            float v1 = off[h] + x1.x * w2[0][h] + x1.y * w2[1][h] + x1.z * w2[2][h] + x1.w * w2[3][h];
            __half2 hv = __floats2half2_rn(v0, v1);
            *(__half2*)&g_bias[((size_t)(b * Hn + h) * Nn + i) * Nn + j] = hv;
        }
    }
}

// ============================================================================
// Kernel 5: tensor-core flash attention with additive bias.
// Block = (i-tile 128, h, b), 8 warps x m16 rows, j-tiles of 64.
// ============================================================================
#define KHI_W 0
#define KLO_W 1280
#define VTHI_W 2560
#define VTLO_W 3712
#define BIAS_W 4864
#define SMEM_W 9472

__global__ __launch_bounds__(256)
void attn_tc()
{
    __shared__ __align__(16) uint32_t S[SMEM_W];
    const int tid = threadIdx.x;
    const int w = tid >> 5, lane = tid & 31;
    const int g = lane >> 2, t = lane & 3;
    const int i0 = blockIdx.x * 128;
    const int bh = blockIdx.z * Hn + blockIdx.y;

    // Q fragments (2 k-tiles x hi/lo), loaded once
    const uint32_t* q32h = (const uint32_t*)g_qhi;
    const uint32_t* q32l = (const uint32_t*)g_qlo;
    const int rowA = bh * Nn + i0 + w * 16 + g;
    const int rowB = rowA + 8;
    uint32_t aQh[2][4], aQl[2][4];
#pragma unroll
    for (int kt = 0; kt < 2; kt++) {
        aQh[kt][0] = q32h[rowA * 16 + kt * 8 + t];
        aQh[kt][1] = q32h[rowB * 16 + kt * 8 + t];
        aQh[kt][2] = q32h[rowA * 16 + kt * 8 + 4 + t];
        aQh[kt][3] = q32h[rowB * 16 + kt * 8 + 4 + t];
        aQl[kt][0] = q32l[rowA * 16 + kt * 8 + t];
        aQl[kt][1] = q32l[rowB * 16 + kt * 8 + t];
        aQl[kt][2] = q32l[rowA * 16 + kt * 8 + 4 + t];
        aQl[kt][3] = q32l[rowB * 16 + kt * 8 + 4 + t];
    }

    float O[4][4] = {};
    float mA = -1e30f, mB = -1e30f, lA = 0.f, lB = 0.f;

    const uint4* kh4 = (const uint4*)g_khi;
    const uint4* kl4 = (const uint4*)g_klo;
    const uint4* vh4 = (const uint4*)g_vthi;
    const uint4* vl4 = (const uint4*)g_vtlo;
    const uint4* bg4 = (const uint4*)g_bias;

    for (int jt = 0; jt < 16; jt++) {
        const int j0 = jt * 64;
        // ---- stage K hi/lo: 64 rows x 4 uint4 each ----
        {
            int row = tid >> 2, c = tid & 3;
            uint4 v1 = kh4[(bh * Nn + j0 + row) * 4 + c];
            uint4 v2 = kl4[(bh * Nn + j0 + row) * 4 + c];
            *(uint4*)&S[KHI_W + row * 20 + c * 4] = v1;
            *(uint4*)&S[KLO_W + row * 20 + c * 4] = v2;
        }
        // ---- stage Vt hi/lo: 32 rows(d) x 8 uint4 ----
        {
            int d = tid >> 3, c = tid & 7;
            uint4 v1 = vh4[(bh * Dn + d) * 128 + jt * 8 + c];
            uint4 v2 = vl4[(bh * Dn + d) * 128 + jt * 8 + c];
            *(uint4*)&S[VTHI_W + d * 36 + c * 4] = v1;
            *(uint4*)&S[VTLO_W + d * 36 + c * 4] = v2;
        }
        // ---- stage bias: 128 rows x 8 uint4 ----
#pragma unroll
        for (int r = 0; r < 4; r++) {
            int idx = tid + r * 256;
            int row = idx >> 3, c = idx & 7;
            uint4 v = bg4[((size_t)(bh * Nn) + i0 + row) * 128 + jt * 8 + c];
            *(uint4*)&S[BIAS_W + row * 36 + c * 4] = v;
        }
        __syncthreads();

        // ---- QK^T (3-term split) ----
        float c_[8][4] = {};
#pragma unroll
        for (int nt = 0; nt < 8; nt++) {
#pragma unroll
            for (int kt = 0; kt < 2; kt++) {
                int kw = (nt * 8 + g) * 20 + kt * 8 + t;
                uint32_t bh0 = S[KHI_W + kw], bh1 = S[KHI_W + kw + 4];
                uint32_t bl0 = S[KLO_W + kw], bl1 = S[KLO_W + kw + 4];
                MMA(c_[nt], aQh[kt], bh0, bh1);
                MMA(c_[nt], aQl[kt], bh0, bh1);
                MMA(c_[nt], aQh[kt], bl0, bl1);
            }
        }
        // ---- + bias (fp16, log2-domain) ----
        const int biA = (w * 16 + g) * 36;
        const int biB = (w * 16 + g + 8) * 36;
#pragma unroll
        for (int nt = 0; nt < 8; nt++) {
            uint32_t u0 = S[BIAS_W + biA + nt * 4 + t];
            uint32_t u1 = S[BIAS_W + biB + nt * 4 + t];
            __half2 h0 = *(__half2*)&u0;
            __half2 h1 = *(__half2*)&u1;
            c_[nt][0] += __low2float(h0);
            c_[nt][1] += __high2float(h0);
            c_[nt][2] += __low2float(h1);
            c_[nt][3] += __high2float(h1);
        }
        // ---- online softmax (log2 domain) ----
        float tA = -1e30f, tB = -1e30f;
#pragma unroll
        for (int nt = 0; nt < 8; nt++) {
            tA = fmaxf(tA, fmaxf(c_[nt][0], c_[nt][1]));
            tB = fmaxf(tB, fmaxf(c_[nt][2], c_[nt][3]));
        }
        tA = fmaxf(tA, __shfl_xor_sync(0xffffffffu, tA, 1));
        tA = fmaxf(tA, __shfl_xor_sync(0xffffffffu, tA, 2));
        tB = fmaxf(tB, __shfl_xor_sync(0xffffffffu, tB, 1));
        tB = fmaxf(tB, __shfl_xor_sync(0xffffffffu, tB, 2));
        float mnA = fmaxf(mA, tA), mnB = fmaxf(mB, tB);
        float cA = ex2(mA - mnA), cB = ex2(mB - mnB);
        mA = mnA; mB = mnB;
        lA *= cA; lB *= cB;
#pragma unroll
        for (int dnt = 0; dnt < 4; dnt++) {
            O[dnt][0] *= cA; O[dnt][1] *= cA;
            O[dnt][2] *= cB; O[dnt][3] *= cB;
        }
        // ---- P = exp2(s - m), pack to bf16 hi/lo (A-frag layout) ----
        uint32_t PH[8], PH2[8], PL[8], PL2[8];
#pragma unroll
        for (int nt = 0; nt < 8; nt++) {
            float p0 = ex2(c_[nt][0] - mA), p1 = ex2(c_[nt][1] - mA);
            float p2 = ex2(c_[nt][2] - mB), p3 = ex2(c_[nt][3] - mB);
            lA += p0 + p1;
            lB += p2 + p3;
            __nv_bfloat162 x01 = __floats2bfloat162_rn(p0, p1);
            __nv_bfloat162 x23 = __floats2bfloat162_rn(p2, p3);
            PH[nt]  = bits2(x01);
            PH2[nt] = bits2(x23);
            PL[nt]  = bits2(__floats2bfloat162_rn(p0 - __low2float(x01), p1 - __high2float(x01)));
            PL2[nt] = bits2(__floats2bfloat162_rn(p2 - __low2float(x23), p3 - __high2float(x23)));
        }
        // ---- PV (3-term split) ----
#pragma unroll
        for (int dnt = 0; dnt < 4; dnt++) {
#pragma unroll
            for (int u = 0; u < 4; u++) {
                int vw = (dnt * 8 + g) * 36 + u * 8 + t;
                uint32_t vh0 = S[VTHI_W + vw], vh1 = S[VTHI_W + vw + 4];
                uint32_t vl0 = S[VTLO_W + vw], vl1 = S[VTLO_W + vw + 4];
                uint32_t aP[4]  = {PH[2 * u], PH2[2 * u], PH[2 * u + 1], PH2[2 * u + 1]};
                uint32_t aPl[4] = {PL[2 * u], PL2[2 * u], PL[2 * u + 1], PL2[2 * u + 1]};
                MMA(O[dnt], aP, vh0, vh1);
                MMA(O[dnt], aPl, vh0, vh1);
                MMA(O[dnt], aP, vl0, vl1);
            }
        }
        __syncthreads();
    }

    // ---- epilogue ----
    lA += __shfl_xor_sync(0xffffffffu, lA, 1);
    lA += __shfl_xor_sync(0xffffffffu, lA, 2);
    lB += __shfl_xor_sync(0xffffffffu, lB, 1);
    lB += __shfl_xor_sync(0xffffffffu, lB, 2);
    const float iA = 1.f / lA, iB = 1.f / lB;
#pragma unroll
    for (int dnt = 0; dnt < 4; dnt++) {
        float2 o1, o2;
        o1.x = O[dnt][0] * iA; o1.y = O[dnt][1] * iA;
        o2.x = O[dnt][2] * iB; o2.y = O[dnt][3] * iB;
        *(float2*)&d_ctx[rowA * Dn + dnt * 8 + 2 * t] = o1;
        *(float2*)&d_ctx[rowB * Dn + dnt * 8 + 2 * t] = o2;
    }
}

// ============================================================================
// Kernel 6: scalar output projection + residual (R1, known-good)
// ============================================================================
__global__ __launch_bounds__(256)
void gemm_out(const float* __restrict__ X,
              const float* __restrict__ Wo, const float* __restrict__ bo,
              float* __restrict__ Out)
{
    __shared__ float As[BK][BM + 4];
    __shared__ float Bs[BK][BN];

    const int tid  = threadIdx.x;
    const int row0 = blockIdx.y * BM;
    const int col0 = blockIdx.x * BN;
    const int tx = tid & 15;
    const int ty = tid >> 4;

    const int a_m = tid >> 2;
    const int a_k = (tid & 3) * 4;
    const int b_k = tid >> 4;
    const int b_n = (tid & 15) * 4;

    const int am_g = row0 + a_m;
    const int am_b = am_g >> 10, am_n = am_g & 1023;

    float acc[4][4] = {};

    for (int k0 = 0; k0 < En; k0 += BK) {
        int k  = k0 + a_k;
        int hh = k >> 5, dd = k & 31;
        float4 av = *(const float4*)&d_ctx[((am_b * Hn + hh) * Nn + am_n) * Dn + dd];
        As[a_k + 0][a_m] = av.x;
        As[a_k + 1][a_m] = av.y;
        As[a_k + 2][a_m] = av.z;
        As[a_k + 3][a_m] = av.w;
        *(float4*)&Bs[b_k][b_n] = *(const float4*)&Wo[(k0 + b_k) * En + col0 + b_n];
        __syncthreads();
#pragma unroll
        for (int kk = 0; kk < BK; kk++) {
            float4 a4 = *(const float4*)&As[kk][ty * 4];
            float4 b4 = *(const float4*)&Bs[kk][tx * 4];
            acc[0][0] += a4.x * b4.x; acc[0][1] += a4.x * b4.y; acc[0][2] += a4.x * b4.z; acc[0][3] += a4.x * b4.w;
            acc[1][0] += a4.y * b4.x; acc[1][1] += a4.y * b4.y; acc[1][2] += a4.y * b4.z; acc[1][3] += a4.y * b4.w;
            acc[2][0] += a4.z * b4.x; acc[2][1] += a4.z * b4.y; acc[2][2] += a4.z * b4.z; acc[2][3] += a4.z * b4.w;
            acc[3][0] += a4.w * b4.x; acc[3][1] += a4.w * b4.y; acc[3][2] += a4.w * b4.z; acc[3][3] += a4.w * b4.w;
        }
        __syncthreads();
    }

    const int c = col0 + tx * 4;
    float4 bz = *(const float4*)&bo[c];
#pragma unroll
    for (int i = 0; i < 4; i++) {
        int m = row0 + ty * 4 + i;
        float4 xr = *(const float4*)&X[m * En + c];
        float4 o;
        o.x = acc[i][0] + bz.x + xr.x;
        o.y = acc[i][1] + bz.y + xr.y;
        o.z = acc[i][2] + bz.z + xr.z;
        o.w = acc[i][3] + bz.w + xr.w;
        *(float4*)&Out[m * En + c] = o;
    }
}

// ============================================================================
extern "C" void kernel_launch(void* const* d_in, const int* in_sizes, int n_in,
                              void* d_out, int out_size)
{
    const float* x   = (const float*)d_in[0];
    const float* adj = (const float*)d_in[1];
    const float* Wq  = (const float*)d_in[2];
    const float* bq  = (const float*)d_in[3];
    const float* Wk  = (const float*)d_in[4];
    const float* bk  = (const float*)d_in[5];
    const float* Wv  = (const float*)d_in[6];
    const float* bv  = (const float*)d_in[7];
    const float* Wo  = (const float*)d_in[8];
    const float* bo  = (const float*)d_in[9];
    const float* Wa  = (const float*)d_in[10];
    const float* ba  = (const float*)d_in[11];
    float* out = (float*)d_out;

    dim3 gq(En / BN, (Bn * Nn) / BM, 3);
    gemm_qkv<<<gq, 256>>>(x, Wq, bq, Wk, bk, Wv, bv);

    convert_qk<<<QSZ / 4 / 256, 256>>>();
    transpose_v<<<Bn * Hn * (Nn / 32), 256>>>();
    bias_pre<<<Bn * Nn, 256>>>(adj, Wa, ba);

    dim3 ga(Nn / 128, Hn, Bn);
    attn_tc<<<ga, 256>>>();

    dim3 go(En / BN, (Bn * Nn) / BM);
    gemm_out<<<go, 256>>>(x, Wo, bo, out);
}

// round 5
// speedup vs baseline: 2.4304x; 1.1492x over previous
#include <cuda_runtime.h>
#include <cuda_bf16.h>
#include <cuda_fp16.h>
#include <cstdint>

#define Bn 8
#define Nn 1024
#define En 256
#define Hn 8
#define Dn 32
#define Cn 4

#define QSZ (Bn * Hn * Nn * Dn)            // 2M elems
__device__ float d_V[QSZ];
__device__ __nv_bfloat16 g_xhi[Bn * Nn * En], g_xlo[Bn * Nn * En];
__device__ __nv_bfloat16 g_qhi[QSZ], g_qlo[QSZ];
__device__ __nv_bfloat16 g_khi[QSZ], g_klo[QSZ];
__device__ __nv_bfloat16 g_vthi[QSZ], g_vtlo[QSZ];   // [B,H,D,N]
__device__ __nv_bfloat16 g_chi[Bn * Nn * En], g_clo[Bn * Nn * En];
__device__ __nv_bfloat16 g_wthi[4 * En * En], g_wtlo[4 * En * En];  // W^T splits
__device__ __half g_bias[(size_t)Bn * Hn * Nn * Nn]; // 134MB, log2e-scaled

#define SCALEQ 0.25506807163967554f   // 1/sqrt(32) * log2e
#define LOG2E  1.4426950408889634f

__device__ __forceinline__ float ex2(float x) {
    float y;
    asm("ex2.approx.f32 %0, %1;" : "=f"(y) : "f"(x));
    return y;
}
__device__ __forceinline__ uint32_t bits2(__nv_bfloat162 v) {
    return *reinterpret_cast<uint32_t*>(&v);
}
__device__ __forceinline__ uint2 pack4bf(float a, float b, float c, float d) {
    uint2 r;
    r.x = bits2(__floats2bfloat162_rn(a, b));
    r.y = bits2(__floats2bfloat162_rn(c, d));
    return r;
}
// split pair -> (hi bits, lo bits)
__device__ __forceinline__ void split2(float a, float b, uint32_t& h, uint32_t& l) {
    __nv_bfloat162 hp = __floats2bfloat162_rn(a, b);
    h = bits2(hp);
    l = bits2(__floats2bfloat162_rn(a - __low2float(hp), b - __high2float(hp)));
}

#define MMA(c, a, b0, b1)                                                     \
    asm volatile("mma.sync.aligned.m16n8k16.row.col.f32.bf16.bf16.f32 "       \
        "{%0,%1,%2,%3}, {%4,%5,%6,%7}, {%8,%9}, {%0,%1,%2,%3};"               \
        : "+f"((c)[0]), "+f"((c)[1]), "+f"((c)[2]), "+f"((c)[3])              \
        : "r"((a)[0]), "r"((a)[1]), "r"((a)[2]), "r"((a)[3]), "r"(b0), "r"(b1))

// ============================================================================
// convert x -> bf16 hi/lo
// ============================================================================
__global__ __launch_bounds__(256)
void convert_x(const float* __restrict__ x)
{
    int i = blockIdx.x * 256 + threadIdx.x;   // per float4
    float4 v = ((const float4*)x)[i];
    float f[4] = {v.x, v.y, v.z, v.w};
    float hi[4], lo[4];
#pragma unroll
    for (int t = 0; t < 4; t++) {
        hi[t] = __bfloat162float(__float2bfloat16_rn(f[t]));
        lo[t] = f[t] - hi[t];
    }
    ((uint2*)g_xhi)[i] = pack4bf(hi[0], hi[1], hi[2], hi[3]);
    ((uint2*)g_xlo)[i] = pack4bf(lo[0], lo[1], lo[2], lo[3]);
}

// ============================================================================
// convert W -> W^T bf16 hi/lo (32x32 tiles)
// ============================================================================
__global__ __launch_bounds__(256)
void convert_wt(const float* __restrict__ W0, const float* __restrict__ W1,
                const float* __restrict__ W2, const float* __restrict__ W3)
{
    __shared__ float T[32][33];
    const int z = blockIdx.x >> 6;
    const int tile = blockIdx.x & 63;
    const int k0 = (tile >> 3) * 32;
    const int n0 = (tile & 7) * 32;
    const float* W = (z == 0) ? W0 : (z == 1) ? W1 : (z == 2) ? W2 : W3;
    const int tid = threadIdx.x;
    {
        int r = tid >> 3, c4 = tid & 7;
        float4 v = *(const float4*)&W[(k0 + r) * En + n0 + c4 * 4];
        T[r][c4 * 4 + 0] = v.x; T[r][c4 * 4 + 1] = v.y;
        T[r][c4 * 4 + 2] = v.z; T[r][c4 * 4 + 3] = v.w;
    }
    __syncthreads();
    {
        int r = tid >> 3, c4 = tid & 7;    // r = n index, c4 -> 4 k's
        float f[4], hi[4], lo[4];
#pragma unroll
        for (int u = 0; u < 4; u++) {
            f[u] = T[c4 * 4 + u][r];
            hi[u] = __bfloat162float(__float2bfloat16_rn(f[u]));
            lo[u] = f[u] - hi[u];
        }
        int off = z * En * En + (n0 + r) * En + k0 + c4 * 4;
        *(uint2*)&g_wthi[off] = pack4bf(hi[0], hi[1], hi[2], hi[3]);
        *(uint2*)&g_wtlo[off] = pack4bf(lo[0], lo[1], lo[2], lo[3]);
    }
}

// ============================================================================
// tensor-core split-bf16 GEMM: C[128x64] tile of A[8192x256] @ B^T.
// MODE 0: QKV (z=blockIdx.z; epilogue -> split Q(scaled)/K, fp32 V)
// MODE 1: out-proj (A=g_chi/clo, W slot 3; epilogue -> +bo +x -> out)
// ============================================================================
#define GA_HI 0
#define GA_LO 2560
#define GB_HI 5120
#define GB_LO 6400
#define GSM_W 7680

template <int MODE>
__global__ __launch_bounds__(256)
void gemm_tc(const float* __restrict__ bias0, const float* __restrict__ bias1,
             const float* __restrict__ bias2,
             const float* __restrict__ X, float* __restrict__ OutR)
{
    __shared__ __align__(16) uint32_t S[GSM_W];
    const int tid = threadIdx.x;
    const int w = tid >> 5, lane = tid & 31;
    const int g = lane >> 2, t = lane & 3;
    const int row0 = blockIdx.y * 128;
    const int col0 = blockIdx.x * 64;
    const int z = (MODE == 0) ? blockIdx.z : 3;

    const uint4* ah4 = (const uint4*)((MODE == 0) ? g_xhi : g_chi);
    const uint4* al4 = (const uint4*)((MODE == 0) ? g_xlo : g_clo);
    const uint4* bh4 = (const uint4*)(g_wthi + z * En * En);
    const uint4* bl4 = (const uint4*)(g_wtlo + z * En * En);

    float c_[8][4] = {};

    const int a_row = tid >> 1;
    const int a_c4 = (tid & 1) * 2;
    const int b_row = tid >> 2;
    const int b_c4 = tid & 3;

    for (int kc = 0; kc < 8; kc++) {
        // stage A: 128 rows x 4 uint4 (32 bf16), hi+lo
        {
            size_t si = (size_t)(row0 + a_row) * 32 + kc * 4 + a_c4;
            *(uint4*)&S[GA_HI + a_row * 20 + a_c4 * 4] = ah4[si];
            *(uint4*)&S[GA_HI + a_row * 20 + (a_c4 + 1) * 4] = ah4[si + 1];
            *(uint4*)&S[GA_LO + a_row * 20 + a_c4 * 4] = al4[si];
            *(uint4*)&S[GA_LO + a_row * 20 + (a_c4 + 1) * 4] = al4[si + 1];
        }
        // stage B: 64 rows x 4 uint4, hi+lo
        {
            size_t si = (size_t)(col0 + b_row) * 32 + kc * 4 + b_c4;
            *(uint4*)&S[GB_HI + b_row * 20 + b_c4 * 4] = bh4[si];
            *(uint4*)&S[GB_LO + b_row * 20 + b_c4 * 4] = bl4[si];
        }
        __syncthreads();
#pragma unroll
        for (int kt = 0; kt < 2; kt++) {
            const int aw = (w * 16 + g) * 20 + kt * 8 + t;
            uint32_t ah[4], al[4];
            ah[0] = S[GA_HI + aw];       ah[1] = S[GA_HI + aw + 160];
            ah[2] = S[GA_HI + aw + 4];   ah[3] = S[GA_HI + aw + 164];
            al[0] = S[GA_LO + aw];       al[1] = S[GA_LO + aw + 160];
            al[2] = S[GA_LO + aw + 4];   al[3] = S[GA_LO + aw + 164];
#pragma unroll
            for (int nt = 0; nt < 8; nt++) {
                const int kw = (nt * 8 + g) * 20 + kt * 8 + t;
                uint32_t b0h = S[GB_HI + kw], b1h = S[GB_HI + kw + 4];
                uint32_t b0l = S[GB_LO + kw], b1l = S[GB_LO + kw + 4];
                MMA(c_[nt], ah, b0h, b1h);
                MMA(c_[nt], al, b0h, b1h);
                MMA(c_[nt], ah, b0l, b1l);
            }
        }
        __syncthreads();
    }

    // ---- epilogue ----
    const int m = row0 + w * 16 + g;              // global row (rowA); rowB = m+8
    if (MODE == 0) {
        const float* bias = (z == 0) ? bias0 : (z == 1) ? bias1 : bias2;
        const int b = m >> 10, n = m & 1023;
#pragma unroll
        for (int nt = 0; nt < 8; nt++) {
            int col = col0 + nt * 8 + 2 * t;
            float bz0 = bias[col], bz1 = bias[col + 1];
            float v0 = c_[nt][0] + bz0, v1 = c_[nt][1] + bz1;
            float v2 = c_[nt][2] + bz0, v3 = c_[nt][3] + bz1;
            int h = col >> 5, dd = col & 31;
            size_t oA = ((size_t)(b * Hn + h) * Nn + n) * Dn + dd;
            size_t oB = oA + 8 * Dn;
            if (z == 0) {
                v0 *= SCALEQ; v1 *= SCALEQ; v2 *= SCALEQ; v3 *= SCALEQ;
                uint32_t hA, lA, hB, lB;
                split2(v0, v1, hA, lA);
                split2(v2, v3, hB, lB);
                *(uint32_t*)&g_qhi[oA] = hA; *(uint32_t*)&g_qlo[oA] = lA;
                *(uint32_t*)&g_qhi[oB] = hB; *(uint32_t*)&g_qlo[oB] = lB;
            } else if (z == 1) {
                uint32_t hA, lA, hB, lB;
                split2(v0, v1, hA, lA);
                split2(v2, v3, hB, lB);
                *(uint32_t*)&g_khi[oA] = hA; *(uint32_t*)&g_klo[oA] = lA;
                *(uint32_t*)&g_khi[oB] = hB; *(uint32_t*)&g_klo[oB] = lB;
            } else {
                float2 p0 = {v0, v1}, p1 = {v2, v3};
                *(float2*)&d_V[oA] = p0;
                *(float2*)&d_V[oB] = p1;
            }
        }
    } else {
#pragma unroll
        for (int nt = 0; nt < 8; nt++) {
            int col = col0 + nt * 8 + 2 * t;
            float bz0 = bias0[col], bz1 = bias0[col + 1];
            float2 xA = *(const float2*)&X[(size_t)m * En + col];
            float2 xB = *(const float2*)&X[(size_t)(m + 8) * En + col];
            float2 oA = {c_[nt][0] + bz0 + xA.x, c_[nt][1] + bz1 + xA.y};
            float2 oB = {c_[nt][2] + bz0 + xB.x, c_[nt][3] + bz1 + xB.y};
            *(float2*)&OutR[(size_t)m * En + col] = oA;
            *(float2*)&OutR[(size_t)(m + 8) * En + col] = oB;
        }
    }
}

// ============================================================================
// transpose V to [B,H,D,N] + split
// ============================================================================
__global__ __launch_bounds__(256)
void transpose_v()
{
    __shared__ float T[32][36];
    const int tid = threadIdx.x;
    const int blk = blockIdx.x;
    const int bh = blk >> 5, jt = blk & 31;
    const int j0 = jt * 32;
    {
        int r = tid >> 3, c = tid & 7;
        float4 v = *(const float4*)&d_V[(bh * Nn + j0 + r) * Dn + c * 4];
        *(float4*)&T[r][c * 4] = v;
    }
    __syncthreads();
    {
        int d = tid >> 3, c = tid & 7;
        float f[4], hi[4], lo[4];
#pragma unroll
        for (int u = 0; u < 4; u++) {
            f[u] = T[c * 4 + u][d];
            hi[u] = __bfloat162float(__float2bfloat16_rn(f[u]));
            lo[u] = f[u] - hi[u];
        }
        int off = (bh * Dn + d) * Nn + j0 + c * 4;
        *(uint2*)&g_vthi[off] = pack4bf(hi[0], hi[1], hi[2], hi[3]);
        *(uint2*)&g_vtlo[off] = pack4bf(lo[0], lo[1], lo[2], lo[3]);
    }
}

// ============================================================================
// bias precompute  bias[b,h,i,j] = (adj[b,i,j,:]@Wa[:,h] + ba[h])*log2e  (fp16)
// ============================================================================
__global__ __launch_bounds__(256)
void bias_pre(const float* __restrict__ adj, const float* __restrict__ Wa,
              const float* __restrict__ ba)
{
    const int tid = threadIdx.x;
    const int b = blockIdx.x >> 10;
    const int i = blockIdx.x & 1023;
    float w2[Cn][Hn], off[Hn];
#pragma unroll
    for (int h = 0; h < Hn; h++) {
        off[h] = ba[h] * LOG2E;
#pragma unroll
        for (int c = 0; c < Cn; c++) w2[c][h] = Wa[c * Hn + h] * LOG2E;
    }
    const float4* a4 = (const float4*)&adj[(size_t)(b * Nn + i) * Nn * Cn];
#pragma unroll
    for (int r = 0; r < 2; r++) {
        int j = (tid + r * 256) * 2;
        float4 x0 = a4[j];
        float4 x1 = a4[j + 1];
#pragma unroll
        for (int h = 0; h < Hn; h++) {
            float v0 = off[h] + x0.x * w2[0][h] + x0.y * w2[1][h] + x0.z * w2[2][h] + x0.w * w2[3][h];
            float v1 = off[h] + x1.x * w2[0][h] + x1.y * w2[1][h] + x1.z * w2[2][h] + x1.w * w2[3][h];
            __half2 hv = __floats2half2_rn(v0, v1);
            *(__half2*)&g_bias[((size_t)(b * Hn + h) * Nn + i) * Nn + j] = hv;
        }
    }
}

// ============================================================================
// tensor-core flash attention with additive bias (unchanged from R4 except
// epilogue writes split bf16 ctx row-major for the out-proj GEMM).
// ============================================================================
#define KHI_W 0
#define KLO_W 1280
#define VTHI_W 2560
#define VTLO_W 3712
#define BIAS_W 4864
#define SMEM_W 9472

__global__ __launch_bounds__(256)
void attn_tc()
{
    __shared__ __align__(16) uint32_t S[SMEM_W];
    const int tid = threadIdx.x;
    const int w = tid >> 5, lane = tid & 31;
    const int g = lane >> 2, t = lane & 3;
    const int i0 = blockIdx.x * 128;
    const int bh = blockIdx.z * Hn + blockIdx.y;

    const uint32_t* q32h = (const uint32_t*)g_qhi;
    const uint32_t* q32l = (const uint32_t*)g_qlo;
    const int rowA = bh * Nn + i0 + w * 16 + g;
    const int rowB = rowA + 8;
    uint32_t aQh[2][4], aQl[2][4];
#pragma unroll
    for (int kt = 0; kt < 2; kt++) {
        aQh[kt][0] = q32h[rowA * 16 + kt * 8 + t];
        aQh[kt][1] = q32h[rowB * 16 + kt * 8 + t];
        aQh[kt][2] = q32h[rowA * 16 + kt * 8 + 4 + t];
        aQh[kt][3] = q32h[rowB * 16 + kt * 8 + 4 + t];
        aQl[kt][0] = q32l[rowA * 16 + kt * 8 + t];
        aQl[kt][1] = q32l[rowB * 16 + kt * 8 + t];
        aQl[kt][2] = q32l[rowA * 16 + kt * 8 + 4 + t];
        aQl[kt][3] = q32l[rowB * 16 + kt * 8 + 4 + t];
    }

    float O[4][4] = {};
    float mA = -1e30f, mB = -1e30f, lA = 0.f, lB = 0.f;

    const uint4* kh4 = (const uint4*)g_khi;
    const uint4* kl4 = (const uint4*)g_klo;
    const uint4* vh4 = (const uint4*)g_vthi;
    const uint4* vl4 = (const uint4*)g_vtlo;
    const uint4* bg4 = (const uint4*)g_bias;

    for (int jt = 0; jt < 16; jt++) {
        const int j0 = jt * 64;
        {
            int row = tid >> 2, c = tid & 3;
            uint4 v1 = kh4[(bh * Nn + j0 + row) * 4 + c];
            uint4 v2 = kl4[(bh * Nn + j0 + row) * 4 + c];
            *(uint4*)&S[KHI_W + row * 20 + c * 4] = v1;
            *(uint4*)&S[KLO_W + row * 20 + c * 4] = v2;
        }
        {
            int d = tid >> 3, c = tid & 7;
            uint4 v1 = vh4[(bh * Dn + d) * 128 + jt * 8 + c];
            uint4 v2 = vl4[(bh * Dn + d) * 128 + jt * 8 + c];
            *(uint4*)&S[VTHI_W + d * 36 + c * 4] = v1;
            *(uint4*)&S[VTLO_W + d * 36 + c * 4] = v2;
        }
#pragma unroll
        for (int r = 0; r < 4; r++) {
            int idx = tid + r * 256;
            int row = idx >> 3, c = idx & 7;
            uint4 v = bg4[((size_t)(bh * Nn) + i0 + row) * 128 + jt * 8 + c];
            *(uint4*)&S[BIAS_W + row * 36 + c * 4] = v;
        }
        __syncthreads();

        float c_[8][4] = {};
#pragma unroll
        for (int nt = 0; nt < 8; nt++) {
#pragma unroll
            for (int kt = 0; kt < 2; kt++) {
                int kw = (nt * 8 + g) * 20 + kt * 8 + t;
                uint32_t bh0 = S[KHI_W + kw], bh1 = S[KHI_W + kw + 4];
                uint32_t bl0 = S[KLO_W + kw], bl1 = S[KLO_W + kw + 4];
                MMA(c_[nt], aQh[kt], bh0, bh1);
                MMA(c_[nt], aQl[kt], bh0, bh1);
                MMA(c_[nt], aQh[kt], bl0, bl1);
            }
        }
        const int biA = (w * 16 + g) * 36;
        const int biB = (w * 16 + g + 8) * 36;
#pragma unroll
        for (int nt = 0; nt < 8; nt++) {
            uint32_t u0 = S[BIAS_W + biA + nt * 4 + t];
            uint32_t u1 = S[BIAS_W + biB + nt * 4 + t];
            __half2 h0 = *(__half2*)&u0;
            __half2 h1 = *(__half2*)&u1;
            c_[nt][0] += __low2float(h0);
            c_[nt][1] += __high2float(h0);
            c_[nt][2] += __low2float(h1);
            c_[nt][3] += __high2float(h1);
        }
        float tA = -1e30f, tB = -1e30f;
#pragma unroll
        for (int nt = 0; nt < 8; nt++) {
            tA = fmaxf(tA, fmaxf(c_[nt][0], c_[nt][1]));
            tB = fmaxf(tB, fmaxf(c_[nt][2], c_[nt][3]));
        }
        tA = fmaxf(tA, __shfl_xor_sync(0xffffffffu, tA, 1));
        tA = fmaxf(tA, __shfl_xor_sync(0xffffffffu, tA, 2));
        tB = fmaxf(tB, __shfl_xor_sync(0xffffffffu, tB, 1));
        tB = fmaxf(tB, __shfl_xor_sync(0xffffffffu, tB, 2));
        float mnA = fmaxf(mA, tA), mnB = fmaxf(mB, tB);
        float cA = ex2(mA - mnA), cB = ex2(mB - mnB);
        mA = mnA; mB = mnB;
        lA *= cA; lB *= cB;
#pragma unroll
        for (int dnt = 0; dnt < 4; dnt++) {
            O[dnt][0] *= cA; O[dnt][1] *= cA;
            O[dnt][2] *= cB; O[dnt][3] *= cB;
        }
        uint32_t PH[8], PH2[8], PL[8], PL2[8];
#pragma unroll
        for (int nt = 0; nt < 8; nt++) {
            float p0 = ex2(c_[nt][0] - mA), p1 = ex2(c_[nt][1] - mA);
            float p2 = ex2(c_[nt][2] - mB), p3 = ex2(c_[nt][3] - mB);
            lA += p0 + p1;
            lB += p2 + p3;
            __nv_bfloat162 x01 = __floats2bfloat162_rn(p0, p1);
            __nv_bfloat162 x23 = __floats2bfloat162_rn(p2, p3);
            PH[nt]  = bits2(x01);
            PH2[nt] = bits2(x23);
            PL[nt]  = bits2(__floats2bfloat162_rn(p0 - __low2float(x01), p1 - __high2float(x01)));
            PL2[nt] = bits2(__floats2bfloat162_rn(p2 - __low2float(x23), p3 - __high2float(x23)));
        }
#pragma unroll
        for (int dnt = 0; dnt < 4; dnt++) {
#pragma unroll
            for (int u = 0; u < 4; u++) {
                int vw = (dnt * 8 + g) * 36 + u * 8 + t;
                uint32_t vh0 = S[VTHI_W + vw], vh1 = S[VTHI_W + vw + 4];
                uint32_t vl0 = S[VTLO_W + vw], vl1 = S[VTLO_W + vw + 4];
                uint32_t aP[4]  = {PH[2 * u], PH2[2 * u], PH[2 * u + 1], PH2[2 * u + 1]};
                uint32_t aPl[4] = {PL[2 * u], PL2[2 * u], PL[2 * u + 1], PL2[2 * u + 1]};
                MMA(O[dnt], aP, vh0, vh1);
                MMA(O[dnt], aPl, vh0, vh1);
                MMA(O[dnt], aP, vl0, vl1);
            }
        }
        __syncthreads();
    }

    lA += __shfl_xor_sync(0xffffffffu, lA, 1);
    lA += __shfl_xor_sync(0xffffffffu, lA, 2);
    lB += __shfl_xor_sync(0xffffffffu, lB, 1);
    lB += __shfl_xor_sync(0xffffffffu, lB, 2);
    const float iA = 1.f / lA, iB = 1.f / lB;

    // epilogue: write ctx split bf16 row-major [b][n][h*32+d]
    const int b = bh >> 3, h = bh & 7;
    const int nA = rowA & (Nn - 1);
    const size_t baseA = ((size_t)b * Nn + nA) * En + h * Dn;
    const size_t baseB = baseA + 8 * En;
#pragma unroll
    for (int dnt = 0; dnt < 4; dnt++) {
        int dd = dnt * 8 + 2 * t;
        uint32_t hA, lA2, hB, lB2;
        split2(O[dnt][0] * iA, O[dnt][1] * iA, hA, lA2);
        split2(O[dnt][2] * iB, O[dnt][3] * iB, hB, lB2);
        *(uint32_t*)&g_chi[baseA + dd] = hA;
        *(uint32_t*)&g_clo[baseA + dd] = lA2;
        *(uint32_t*)&g_chi[baseB + dd] = hB;
        *(uint32_t*)&g_clo[baseB + dd] = lB2;
    }
}

// ============================================================================
extern "C" void kernel_launch(void* const* d_in, const int* in_sizes, int n_in,
                              void* d_out, int out_size)
{
    const float* x   = (const float*)d_in[0];
    const float* adj = (const float*)d_in[1];
    const float* Wq  = (const float*)d_in[2];
    const float* bq  = (const float*)d_in[3];
    const float* Wk  = (const float*)d_in[4];
    const float* bk  = (const float*)d_in[5];
    const float* Wv  = (const float*)d_in[6];
    const float* bv  = (const float*)d_in[7];
    const float* Wo  = (const float*)d_in[8];
    const float* bo  = (const float*)d_in[9];
    const float* Wa  = (const float*)d_in[10];
    const float* ba  = (const float*)d_in[11];
    float* out = (float*)d_out;

    convert_x<<<(Bn * Nn * En / 4) / 256, 256>>>(x);
    convert_wt<<<4 * 64, 256>>>(Wq, Wk, Wv, Wo);

    dim3 gq(En / 64, (Bn * Nn) / 128, 3);
    gemm_tc<0><<<gq, 256>>>(bq, bk, bv, nullptr, nullptr);

    transpose_v<<<Bn * Hn * (Nn / 32), 256>>>();
    bias_pre<<<Bn * Nn, 256>>>(adj, Wa, ba);

    dim3 ga(Nn / 128, Hn, Bn);
    attn_tc<<<ga, 256>>>();

    dim3 go(En / 64, (Bn * Nn) / 128);
    gemm_tc<1><<<go, 256>>>(bo, bo, bo, x, out);
}